// round 15
// baseline (speedup 1.0000x reference)
#include <cuda_runtime.h>
#include <cuda_bf16.h>
#include <math.h>
#include <stdint.h>

#define NUM_HEADS 16
#define DMODEL    1024
#define DK        64
#define BATCH     2
#define SEQ       2048
#define MROWS     (BATCH * SEQ)      // 4096
#define KDIM      1024
#define HSZ       (BATCH * NUM_HEADS * SEQ * DK)   // 4194304
#define XSZ       (MROWS * KDIM)     // 4194304
#define WSZ       (DMODEL * KDIM)    // 1048576

// ---------------- scratch (device globals; no allocation allowed) ----------
__device__ __align__(128) float g_Q[HSZ];                 // fp32 Q [b,h,s,d]
__device__ __align__(128) __nv_bfloat16 g_Khi[HSZ];
__device__ __align__(128) __nv_bfloat16 g_Klo[HSZ];
__device__ __align__(128) __nv_bfloat16 g_Vhi[HSZ];
__device__ __align__(128) __nv_bfloat16 g_Vlo[HSZ];
__device__ __align__(128) __nv_bfloat16 g_Ohi[(size_t)MROWS * DMODEL];
__device__ __align__(128) __nv_bfloat16 g_Olo[(size_t)MROWS * DMODEL];
// pre-split GEMM operands
__device__ __align__(128) __nv_bfloat16 g_Xhi[3 * XSZ];
__device__ __align__(128) __nv_bfloat16 g_Xlo[3 * XSZ];
__device__ __align__(128) __nv_bfloat16 g_Whi[4 * WSZ];
__device__ __align__(128) __nv_bfloat16 g_Wlo[4 * WSZ];

// ==========================================================================
// helpers (arch-agnostic PTX: valid on plain sm_103 target)
// ==========================================================================
__device__ __forceinline__ uint32_t smem_u32(const void* p) {
    uint32_t a;
    asm("{ .reg .u64 t; cvta.to.shared.u64 t, %1; cvt.u32.u64 %0, t; }"
        : "=r"(a) : "l"(p));
    return a;
}

__device__ __forceinline__ void ldsm4(uint32_t* r, uint32_t addr) {
    asm volatile("ldmatrix.sync.aligned.m8n8.x4.shared.b16 {%0,%1,%2,%3}, [%4];"
                 : "=r"(r[0]), "=r"(r[1]), "=r"(r[2]), "=r"(r[3])
                 : "r"(addr));
}

__device__ __forceinline__ void ldsm4t(uint32_t* r, uint32_t addr) {
    asm volatile("ldmatrix.sync.aligned.m8n8.x4.trans.shared.b16 {%0,%1,%2,%3}, [%4];"
                 : "=r"(r[0]), "=r"(r[1]), "=r"(r[2]), "=r"(r[3])
                 : "r"(addr));
}

__device__ __forceinline__ void mma16816(float* c, const uint32_t* a,
                                         uint32_t b0, uint32_t b1) {
    asm volatile(
        "mma.sync.aligned.m16n8k16.row.col.f32.bf16.bf16.f32 "
        "{%0,%1,%2,%3}, {%4,%5,%6,%7}, {%8,%9}, {%0,%1,%2,%3};"
        : "+f"(c[0]), "+f"(c[1]), "+f"(c[2]), "+f"(c[3])
        : "r"(a[0]), "r"(a[1]), "r"(a[2]), "r"(a[3]), "r"(b0), "r"(b1));
}

__device__ __forceinline__ void cpasync16(uint32_t dst, const void* src) {
    asm volatile("cp.async.cg.shared.global [%0], [%1], 16;"
                 :: "r"(dst), "l"(src) : "memory");
}
__device__ __forceinline__ void cp_commit() {
    asm volatile("cp.async.commit_group;" ::: "memory");
}
template <int N>
__device__ __forceinline__ void cp_wait() {
    asm volatile("cp.async.wait_group %0;" :: "n"(N) : "memory");
}

__device__ __forceinline__ float ex2(float x) {
    float r;
    asm("ex2.approx.ftz.f32 %0, %1;" : "=f"(r) : "f"(x));
    return r;
}

__device__ __forceinline__ uint32_t packbf(__nv_bfloat16 a, __nv_bfloat16 b) {
    return (uint32_t)__bfloat16_as_ushort(a) |
           ((uint32_t)__bfloat16_as_ushort(b) << 16);
}

// fp32x4 -> hi bf16x4 (8B) + lo bf16x4 (8B)
__device__ __forceinline__ void cvt_split8b(float4 v, char* hiP, char* loP) {
    __nv_bfloat16 h0 = __float2bfloat16(v.x);
    __nv_bfloat16 h1 = __float2bfloat16(v.y);
    __nv_bfloat16 h2 = __float2bfloat16(v.z);
    __nv_bfloat16 h3 = __float2bfloat16(v.w);
    __nv_bfloat16 l0 = __float2bfloat16(v.x - __bfloat162float(h0));
    __nv_bfloat16 l1 = __float2bfloat16(v.y - __bfloat162float(h1));
    __nv_bfloat16 l2 = __float2bfloat16(v.z - __bfloat162float(h2));
    __nv_bfloat16 l3 = __float2bfloat16(v.w - __bfloat162float(h3));
    *(uint2*)hiP = make_uint2(packbf(h0, h1), packbf(h2, h3));
    *(uint2*)loP = make_uint2(packbf(l0, l1), packbf(l2, l3));
}

// ==========================================================================
// pre-conversion: fp32 -> bf16 hi/lo, 3 inputs (z<3) + 4 weights (z>=3)
// ==========================================================================
__global__ __launch_bounds__(256)
void cvt_kernel(const float* __restrict__ Qin, const float* __restrict__ Kin,
                const float* __restrict__ Vin,
                const float* __restrict__ Wq, const float* __restrict__ Wk,
                const float* __restrict__ Wv, const float* __restrict__ Wo)
{
    const int z = blockIdx.z;
    const float* src;
    __nv_bfloat16 *dhi, *dlo;
    size_t n4;
    if (z < 3) {
        src = (z == 0) ? Qin : (z == 1) ? Kin : Vin;
        dhi = g_Xhi + (size_t)z * XSZ;
        dlo = g_Xlo + (size_t)z * XSZ;
        n4  = XSZ / 4;
    } else {
        const int w = z - 3;
        src = (w == 0) ? Wq : (w == 1) ? Wk : (w == 2) ? Wv : Wo;
        dhi = g_Whi + (size_t)w * WSZ;
        dlo = g_Wlo + (size_t)w * WSZ;
        n4  = WSZ / 4;
    }
    const size_t stride = (size_t)gridDim.x * blockDim.x;
    for (size_t i = (size_t)blockIdx.x * blockDim.x + threadIdx.x; i < n4; i += stride) {
        float4 v = ((const float4*)src)[i];
        cvt_split8b(v, (char*)(dhi + i * 4), (char*)(dlo + i * 4));
    }
}

// ==========================================================================
// Pure-bf16 tensor-core GEMM, cp.async 2-stage, 3 CTAs/SM.
// BM=128 x BN=64, 8 warps 4(m)x2(n), warp tile 32x32 (mapping = R10, proven).
// Per chunk: wait+sync -> MMA -> sync -> cp.async next (writes land async
// during the other stage's MMA; never in the same barrier phase as ldsm).
// ==========================================================================
#define TSTRIDE 80
#define A_TILE  (128 * TSTRIDE)        // 10240
#define B_TILE  (64 * TSTRIDE)         // 5120
#define S_AHI   0
#define S_ALO   A_TILE
#define S_BHI   (2 * A_TILE)
#define S_BLO   (2 * A_TILE + B_TILE)
#define STAGE   (2 * A_TILE + 2 * B_TILE)   // 30720
#define GDSMEM  (2 * STAGE)                 // 61440 dynamic
#define KCHUNK  32

template <bool SPLIT>
__device__ __forceinline__ void gemm_bf16_body(const __nv_bfloat16* __restrict__ Ahig,
                                               const __nv_bfloat16* __restrict__ Alog,
                                               const __nv_bfloat16* __restrict__ Bhig,
                                               const __nv_bfloat16* __restrict__ Blog,
                                               const float* __restrict__ bias,
                                               float* __restrict__ Cf,
                                               __nv_bfloat16* __restrict__ Chi,
                                               __nv_bfloat16* __restrict__ Clo)
{
    extern __shared__ __align__(128) char dsm[];
    const uint32_t sbase = smem_u32(dsm);

    const int t   = threadIdx.x;
    const int l   = t & 31;
    const int wid = t >> 5;
    const int wm  = wid & 3;
    const int wn  = wid >> 2;
    const int rowBlk = blockIdx.y * 128;
    const int colBlk = blockIdx.x * 64;

    // cp.async mapping: row r0 = t>>2 (A also r0+64), 16B granule (t&3)
    const int r0  = t >> 2;              // 0..63
    const int g8  = (t & 3) * 8;         // element offset in 32-elem chunk
    const uint32_t gd = (uint32_t)r0 * TSTRIDE + (uint32_t)(t & 3) * 16;
    const __nv_bfloat16* Ah = Ahig + (size_t)(rowBlk + r0) * KDIM + g8;
    const __nv_bfloat16* Al = Alog + (size_t)(rowBlk + r0) * KDIM + g8;
    const __nv_bfloat16* Bh = Bhig + (size_t)(colBlk + r0) * KDIM + g8;
    const __nv_bfloat16* Bl = Blog + (size_t)(colBlk + r0) * KDIM + g8;

    auto issue = [&](int c) {
        if (c < KCHUNK) {
            const uint32_t stg = sbase + (uint32_t)(c & 1) * STAGE;
            const size_t ko = (size_t)c * 32;
            cpasync16(stg + S_AHI + gd, Ah + ko);
            cpasync16(stg + S_AHI + gd + 64 * TSTRIDE, Ah + (size_t)64 * KDIM + ko);
            cpasync16(stg + S_ALO + gd, Al + ko);
            cpasync16(stg + S_ALO + gd + 64 * TSTRIDE, Al + (size_t)64 * KDIM + ko);
            cpasync16(stg + S_BHI + gd, Bh + ko);
            cpasync16(stg + S_BLO + gd, Bl + ko);
        }
        cp_commit();   // always commit: keeps wait_group<1> counting exact
    };

    float acc[2][4][4];
#pragma unroll
    for (int mi = 0; mi < 2; mi++)
#pragma unroll
        for (int ni = 0; ni < 4; ni++)
#pragma unroll
            for (int k = 0; k < 4; k++) acc[mi][ni][k] = 0.f;

    const uint32_t lr  = (uint32_t)(l & 15);
    const uint32_t lcb = (uint32_t)(l >> 4) * 16;
    const uint32_t aOff = S_AHI + (wm * 32 + lr) * TSTRIDE + lcb;
    const uint32_t bOff = S_BHI + (wn * 32 + lr) * TSTRIDE + lcb;

    issue(0);
    issue(1);

    for (int c = 0; c < KCHUNK; c++) {
        cp_wait<1>();          // chunk c landed
        __syncthreads();

        const uint32_t sb = sbase + (uint32_t)(c & 1) * STAGE;
        const uint32_t aBase = sb + aOff;
        const uint32_t bBase = sb + bOff;
#pragma unroll
        for (int ks = 0; ks < 2; ks++) {
            const uint32_t ko = (uint32_t)ks * 32;
            uint32_t ah[2][4], al[2][4];
#pragma unroll
            for (int mi = 0; mi < 2; mi++) {
                ldsm4(ah[mi], aBase + mi * (16 * TSTRIDE) + ko);
                ldsm4(al[mi], aBase + A_TILE + mi * (16 * TSTRIDE) + ko);
            }
            uint32_t bh[2][4], bl[2][4];
#pragma unroll
            for (int g = 0; g < 2; g++) {
                ldsm4(bh[g], bBase + g * (16 * TSTRIDE) + ko);
                ldsm4(bl[g], bBase + B_TILE + g * (16 * TSTRIDE) + ko);
            }
#pragma unroll
            for (int mi = 0; mi < 2; mi++) {
#pragma unroll
                for (int ni = 0; ni < 4; ni++) {
                    const int g = ni >> 1, s = ni & 1;
                    mma16816(acc[mi][ni], ah[mi], bh[g][s], bh[g][s + 2]);
                    mma16816(acc[mi][ni], ah[mi], bl[g][s], bl[g][s + 2]);
                    mma16816(acc[mi][ni], al[mi], bh[g][s], bh[g][s + 2]);
                }
            }
        }
        __syncthreads();       // all warps done reading stage c&1
        issue(c + 2);          // refill it (lands during next chunk's MMA)
    }

    // ---- epilogue: bias + store ----
#pragma unroll
    for (int mi = 0; mi < 2; mi++) {
        const int rBase = rowBlk + wm * 32 + mi * 16 + (l >> 2);
#pragma unroll
        for (int ni = 0; ni < 4; ni++) {
            const int n = colBlk + wn * 32 + ni * 8 + (l & 3) * 2;
            const float2 bb = *(const float2*)(bias + n);
#pragma unroll
            for (int h2 = 0; h2 < 2; h2++) {
                const int m = rBase + h2 * 8;
                float2 v;
                v.x = acc[mi][ni][h2 * 2 + 0] + bb.x;
                v.y = acc[mi][ni][h2 * 2 + 1] + bb.y;
                if (SPLIT) {
                    const int b = m >> 11;
                    const int s = m & (SEQ - 1);
                    const int h = n >> 6;
                    const int d = n & (DK - 1);
                    const size_t idx = (((size_t)(b * NUM_HEADS + h) * SEQ + s) * DK) + d;
                    if (Chi == nullptr) {
                        *(float2*)&Cf[idx] = v;
                    } else {
                        __nv_bfloat16 hx = __float2bfloat16(v.x);
                        __nv_bfloat16 hy = __float2bfloat16(v.y);
                        __nv_bfloat16 lx = __float2bfloat16(v.x - __bfloat162float(hx));
                        __nv_bfloat16 ly = __float2bfloat16(v.y - __bfloat162float(hy));
                        *(uint32_t*)&Chi[idx] = packbf(hx, hy);
                        *(uint32_t*)&Clo[idx] = packbf(lx, ly);
                    }
                } else {
                    *(float2*)&Cf[(size_t)m * DMODEL + n] = v;
                }
            }
        }
    }
}

__global__ __launch_bounds__(256, 3)
void qkv_tc_kernel(const float* __restrict__ bq,
                   const float* __restrict__ bk,
                   const float* __restrict__ bv)
{
    const int z = blockIdx.z;
    const __nv_bfloat16* Ah = g_Xhi + (size_t)z * XSZ;
    const __nv_bfloat16* Al = g_Xlo + (size_t)z * XSZ;
    const __nv_bfloat16* Bh = g_Whi + (size_t)z * WSZ;
    const __nv_bfloat16* Bl = g_Wlo + (size_t)z * WSZ;
    if (z == 0) {
        gemm_bf16_body<true>(Ah, Al, Bh, Bl, bq, g_Q, nullptr, nullptr);
    } else if (z == 1) {
        gemm_bf16_body<true>(Ah, Al, Bh, Bl, bk, nullptr, g_Khi, g_Klo);
    } else {
        gemm_bf16_body<true>(Ah, Al, Bh, Bl, bv, nullptr, g_Vhi, g_Vlo);
    }
}

__global__ __launch_bounds__(256, 3)
void out_tc_kernel(const float* __restrict__ bo, float* __restrict__ out)
{
    gemm_bf16_body<false>(g_Ohi, g_Olo, g_Whi + 3ull * WSZ, g_Wlo + 3ull * WSZ,
                          bo, out, nullptr, nullptr);
}

// ==========================================================================
// Flash attention (bf16x3), 2 CTAs/SM, base-2 softmax: exact R14 version.
// ==========================================================================
#define FSTR    144
#define FT      (64 * FSTR)            // 9216
#define FQ_HI   0
#define FQ_LO   18432
#define FKV     36864
#define F_KHI   (FKV + 0)
#define F_KLO   (FKV + FT)
#define F_VHI   (FKV + 2 * FT)
#define F_VLO   (FKV + 3 * FT)
#define FSMEM   (FKV + 4 * FT)         // 73728

__global__ __launch_bounds__(256, 2)
void flash_tc_kernel()
{
    extern __shared__ __align__(128) char fsm[];
    const uint32_t sbase = smem_u32(fsm);

    const int t  = threadIdx.x;
    const int l  = t & 31;
    const int w  = t >> 5;
    const int q0 = blockIdx.x * 128;
    const int h  = blockIdx.y;
    const int b  = blockIdx.z;

    const size_t headBase = ((size_t)b * NUM_HEADS + h) * SEQ * DK;
    const float*         Qg  = g_Q   + headBase;
    const __nv_bfloat16* Khi = g_Khi + headBase;
    const __nv_bfloat16* Klo = g_Klo + headBase;
    const __nv_bfloat16* Vhi = g_Vhi + headBase;
    const __nv_bfloat16* Vlo = g_Vlo + headBase;

    const float SCALE2 = 0.125f * 1.4426950408889634f;

    {
        const int row  = t >> 1;
        const int half = (t & 1) * 32;
#pragma unroll
        for (int i = 0; i < 8; i++) {
            float4 q = *(const float4*)&Qg[(size_t)(q0 + row) * DK + half + 4 * i];
            q.x *= SCALE2; q.y *= SCALE2; q.z *= SCALE2; q.w *= SCALE2;
            const uint32_t o = (uint32_t)row * FSTR + (uint32_t)(half + 4 * i) * 2;
            cvt_split8b(q, fsm + FQ_HI + o, fsm + FQ_LO + o);
        }
    }

    float o_[8][4];
#pragma unroll
    for (int j = 0; j < 8; j++)
#pragma unroll
        for (int k = 0; k < 4; k++) o_[j][k] = 0.f;
    float m0 = -1e30f, m1 = -1e30f, l0 = 0.f, l1 = 0.f;

    const uint32_t qbase = sbase + (uint32_t)(w * 16 + (l & 15)) * FSTR
                         + (uint32_t)(l >> 4) * 16;
    const uint32_t lbase = sbase + (uint32_t)(l & 15) * FSTR
                         + (uint32_t)(l >> 4) * 16;
    const uint32_t voff  = (uint32_t)((((l >> 4) & 1) * 8 + (l & 7))) * FSTR
                         + (uint32_t)((l >> 3) & 1) * 16;

    for (int j0 = 0; j0 < SEQ; j0 += 64) {
        {
            const int key = t >> 2;
            const int gr  = (t & 3) * 16;
            const char* kh = (const char*)(Khi + (size_t)(j0 + key) * DK);
            const char* kl = (const char*)(Klo + (size_t)(j0 + key) * DK);
            const char* vh = (const char*)(Vhi + (size_t)(j0 + key) * DK);
            const char* vl = (const char*)(Vlo + (size_t)(j0 + key) * DK);
            const uint32_t so = (uint32_t)key * FSTR;
#pragma unroll
            for (int p = 0; p < 2; p++) {
                const uint32_t cb = (uint32_t)gr + p * 64;
                *(uint4*)(fsm + F_KHI + so + cb) = *(const uint4*)(kh + cb);
                *(uint4*)(fsm + F_KLO + so + cb) = *(const uint4*)(kl + cb);
                *(uint4*)(fsm + F_VHI + so + cb) = *(const uint4*)(vh + cb);
                *(uint4*)(fsm + F_VLO + so + cb) = *(const uint4*)(vl + cb);
            }
        }
        __syncthreads();

        float s[8][4];
#pragma unroll
        for (int j = 0; j < 8; j++)
#pragma unroll
            for (int k = 0; k < 4; k++) s[j][k] = 0.f;

#pragma unroll
        for (int kt = 0; kt < 4; kt++) {
            uint32_t qh[4], ql[4];
            ldsm4(qh, qbase + FQ_HI + kt * 32);
            ldsm4(ql, qbase + FQ_LO + kt * 32);
#pragma unroll
            for (int kg = 0; kg < 4; kg++) {
                uint32_t kh[4], kl[4];
                ldsm4(kh, lbase + F_KHI + kg * (16 * FSTR) + kt * 32);
                ldsm4(kl, lbase + F_KLO + kg * (16 * FSTR) + kt * 32);
#pragma unroll
                for (int ss = 0; ss < 2; ss++) {
                    float* sc = s[2 * kg + ss];
                    mma16816(sc, qh, kh[ss], kh[ss + 2]);
                    mma16816(sc, qh, kl[ss], kl[ss + 2]);
                    mma16816(sc, ql, kh[ss], kh[ss + 2]);
                }
            }
        }

        {
            float mx0 = s[0][0], mx1 = s[0][2];
#pragma unroll
            for (int j = 0; j < 8; j++) {
                mx0 = fmaxf(mx0, fmaxf(s[j][0], s[j][1]));
                mx1 = fmaxf(mx1, fmaxf(s[j][2], s[j][3]));
            }
            mx0 = fmaxf(mx0, __shfl_xor_sync(0xffffffffu, mx0, 1));
            mx0 = fmaxf(mx0, __shfl_xor_sync(0xffffffffu, mx0, 2));
            mx1 = fmaxf(mx1, __shfl_xor_sync(0xffffffffu, mx1, 1));
            mx1 = fmaxf(mx1, __shfl_xor_sync(0xffffffffu, mx1, 2));

            const float mn0 = fmaxf(m0, mx0);
            const float mn1 = fmaxf(m1, mx1);
            const float c0 = ex2(m0 - mn0);
            const float c1 = ex2(m1 - mn1);
            m0 = mn0; m1 = mn1;

            float rs0 = 0.f, rs1 = 0.f;
#pragma unroll
            for (int j = 0; j < 8; j++) {
                s[j][0] = ex2(s[j][0] - mn0);
                s[j][1] = ex2(s[j][1] - mn0);
                s[j][2] = ex2(s[j][2] - mn1);
                s[j][3] = ex2(s[j][3] - mn1);
                rs0 += s[j][0] + s[j][1];
                rs1 += s[j][2] + s[j][3];
            }
            rs0 += __shfl_xor_sync(0xffffffffu, rs0, 1);
            rs0 += __shfl_xor_sync(0xffffffffu, rs0, 2);
            rs1 += __shfl_xor_sync(0xffffffffu, rs1, 1);
            rs1 += __shfl_xor_sync(0xffffffffu, rs1, 2);
            l0 = l0 * c0 + rs0;
            l1 = l1 * c1 + rs1;

#pragma unroll
            for (int j = 0; j < 8; j++) {
                o_[j][0] *= c0; o_[j][1] *= c0;
                o_[j][2] *= c1; o_[j][3] *= c1;
            }
        }

#pragma unroll
        for (int kt = 0; kt < 4; kt++) {
            uint32_t phi[4], plo[4];
#pragma unroll
            for (int half = 0; half < 2; half++) {
                const float* sp = s[2 * kt + half];
#pragma unroll
                for (int rr = 0; rr < 2; rr++) {
                    const float x = sp[2 * rr + 0], y = sp[2 * rr + 1];
                    __nv_bfloat16 hx = __float2bfloat16(x);
                    __nv_bfloat16 hy = __float2bfloat16(y);
                    __nv_bfloat16 lx = __float2bfloat16(x - __bfloat162float(hx));
                    __nv_bfloat16 ly = __float2bfloat16(y - __bfloat162float(hy));
                    phi[2 * half + rr] = packbf(hx, hy);
                    plo[2 * half + rr] = packbf(lx, ly);
                }
            }
#pragma unroll
            for (int dg = 0; dg < 4; dg++) {
                uint32_t vh[4], vl[4];
                const uint32_t va = sbase + voff + kt * (16 * FSTR) + dg * 32;
                ldsm4t(vh, va + F_VHI);
                ldsm4t(vl, va + F_VLO);
#pragma unroll
                for (int ss = 0; ss < 2; ss++) {
                    float* oc = o_[2 * dg + ss];
                    mma16816(oc, phi, vh[ss], vh[ss + 2]);
                    mma16816(oc, phi, vl[ss], vl[ss + 2]);
                    mma16816(oc, plo, vh[ss], vh[ss + 2]);
                }
            }
        }
        __syncthreads();
    }

    {
        const float inv0 = 1.f / l0;
        const float inv1 = 1.f / l1;
        const int r0 = q0 + w * 16 + (l >> 2);
        const int r1 = r0 + 8;
        const size_t ro0 = ((size_t)b * SEQ + r0) * DMODEL;
        const size_t ro1 = ((size_t)b * SEQ + r1) * DMODEL;
#pragma unroll
        for (int j = 0; j < 8; j++) {
            const int d = h * DK + j * 8 + (l & 3) * 2;
            {
                const float x = o_[j][0] * inv0, y = o_[j][1] * inv0;
                __nv_bfloat16 hx = __float2bfloat16(x), hy = __float2bfloat16(y);
                __nv_bfloat16 lx = __float2bfloat16(x - __bfloat162float(hx));
                __nv_bfloat16 ly = __float2bfloat16(y - __bfloat162float(hy));
                *(uint32_t*)&g_Ohi[ro0 + d] = packbf(hx, hy);
                *(uint32_t*)&g_Olo[ro0 + d] = packbf(lx, ly);
            }
            {
                const float x = o_[j][2] * inv1, y = o_[j][3] * inv1;
                __nv_bfloat16 hx = __float2bfloat16(x), hy = __float2bfloat16(y);
                __nv_bfloat16 lx = __float2bfloat16(x - __bfloat162float(hx));
                __nv_bfloat16 ly = __float2bfloat16(y - __bfloat162float(hy));
                *(uint32_t*)&g_Ohi[ro1 + d] = packbf(hx, hy);
                *(uint32_t*)&g_Olo[ro1 + d] = packbf(lx, ly);
            }
        }
    }
}

// ==========================================================================
// launch
// ==========================================================================
extern "C" void kernel_launch(void* const* d_in, const int* in_sizes, int n_in,
                              void* d_out, int out_size)
{
    (void)in_sizes; (void)n_in; (void)out_size;
    const float* Qin = (const float*)d_in[0];
    const float* Kin = (const float*)d_in[1];
    const float* Vin = (const float*)d_in[2];
    const float* Wq  = (const float*)d_in[3];
    const float* bq  = (const float*)d_in[4];
    const float* Wk  = (const float*)d_in[5];
    const float* bk  = (const float*)d_in[6];
    const float* Wv  = (const float*)d_in[7];
    const float* bv  = (const float*)d_in[8];
    const float* Wo  = (const float*)d_in[9];
    const float* bo  = (const float*)d_in[10];
    float* out = (float*)d_out;

    cudaFuncSetAttribute(qkv_tc_kernel,
                         cudaFuncAttributeMaxDynamicSharedMemorySize, GDSMEM);
    cudaFuncSetAttribute(out_tc_kernel,
                         cudaFuncAttributeMaxDynamicSharedMemorySize, GDSMEM);
    cudaFuncSetAttribute(flash_tc_kernel,
                         cudaFuncAttributeMaxDynamicSharedMemorySize, FSMEM);

    dim3 gCvt(512, 1, 7);
    cvt_kernel<<<gCvt, 256>>>(Qin, Kin, Vin, Wq, Wk, Wv, Wo);

    dim3 gProj(DMODEL / 64, MROWS / 128, 3);
    qkv_tc_kernel<<<gProj, 256, GDSMEM>>>(bq, bk, bv);

    dim3 gAttn(SEQ / 128, NUM_HEADS, BATCH);
    flash_tc_kernel<<<gAttn, 256, FSMEM>>>();

    dim3 gOut(DMODEL / 64, MROWS / 128, 1);
    out_tc_kernel<<<gOut, 256, GDSMEM>>>(bo, out);
}

// round 16
// speedup vs baseline: 1.0026x; 1.0026x over previous
#include <cuda_runtime.h>
#include <cuda_bf16.h>
#include <math.h>
#include <stdint.h>

#define NUM_HEADS 16
#define DMODEL    1024
#define DK        64
#define BATCH     2
#define SEQ       2048
#define MROWS     (BATCH * SEQ)      // 4096
#define KDIM      1024
#define HSZ       (BATCH * NUM_HEADS * SEQ * DK)   // 4194304

// ---------------- scratch (device globals; no allocation allowed) ----------
__device__ __align__(128) float g_Q[HSZ];                 // fp32 Q [b,h,s,d]
__device__ __align__(128) __nv_bfloat16 g_Khi[HSZ];
__device__ __align__(128) __nv_bfloat16 g_Klo[HSZ];
__device__ __align__(128) __nv_bfloat16 g_Vhi[HSZ];
__device__ __align__(128) __nv_bfloat16 g_Vlo[HSZ];
__device__ __align__(128) __nv_bfloat16 g_Ohi[(size_t)MROWS * DMODEL];
__device__ __align__(128) __nv_bfloat16 g_Olo[(size_t)MROWS * DMODEL];

// ==========================================================================
// warp-MMA helpers (arch-agnostic PTX: valid on plain sm_103 target)
// ==========================================================================
__device__ __forceinline__ uint32_t smem_u32(const void* p) {
    uint32_t a;
    asm("{ .reg .u64 t; cvta.to.shared.u64 t, %1; cvt.u32.u64 %0, t; }"
        : "=r"(a) : "l"(p));
    return a;
}

__device__ __forceinline__ void ldsm4(uint32_t* r, uint32_t addr) {
    asm volatile("ldmatrix.sync.aligned.m8n8.x4.shared.b16 {%0,%1,%2,%3}, [%4];"
                 : "=r"(r[0]), "=r"(r[1]), "=r"(r[2]), "=r"(r[3])
                 : "r"(addr));
}

__device__ __forceinline__ void ldsm4t(uint32_t* r, uint32_t addr) {
    asm volatile("ldmatrix.sync.aligned.m8n8.x4.trans.shared.b16 {%0,%1,%2,%3}, [%4];"
                 : "=r"(r[0]), "=r"(r[1]), "=r"(r[2]), "=r"(r[3])
                 : "r"(addr));
}

__device__ __forceinline__ void mma16816(float* c, const uint32_t* a,
                                         uint32_t b0, uint32_t b1) {
    asm volatile(
        "mma.sync.aligned.m16n8k16.row.col.f32.bf16.bf16.f32 "
        "{%0,%1,%2,%3}, {%4,%5,%6,%7}, {%8,%9}, {%0,%1,%2,%3};"
        : "+f"(c[0]), "+f"(c[1]), "+f"(c[2]), "+f"(c[3])
        : "r"(a[0]), "r"(a[1]), "r"(a[2]), "r"(a[3]), "r"(b0), "r"(b1));
}

__device__ __forceinline__ float ex2(float x) {
    float r;
    asm("ex2.approx.ftz.f32 %0, %1;" : "=f"(r) : "f"(x));
    return r;
}

__device__ __forceinline__ uint32_t packbf(__nv_bfloat16 a, __nv_bfloat16 b) {
    return (uint32_t)__bfloat16_as_ushort(a) |
           ((uint32_t)__bfloat16_as_ushort(b) << 16);
}

// fp32x4 -> hi bf16x4 (8B) + lo bf16x4 (8B)
__device__ __forceinline__ void cvt_split8b(float4 v, char* hiP, char* loP) {
    __nv_bfloat16 h0 = __float2bfloat16(v.x);
    __nv_bfloat16 h1 = __float2bfloat16(v.y);
    __nv_bfloat16 h2 = __float2bfloat16(v.z);
    __nv_bfloat16 h3 = __float2bfloat16(v.w);
    __nv_bfloat16 l0 = __float2bfloat16(v.x - __bfloat162float(h0));
    __nv_bfloat16 l1 = __float2bfloat16(v.y - __bfloat162float(h1));
    __nv_bfloat16 l2 = __float2bfloat16(v.z - __bfloat162float(h2));
    __nv_bfloat16 l3 = __float2bfloat16(v.w - __bfloat162float(h3));
    *(uint2*)hiP = make_uint2(packbf(h0, h1), packbf(h2, h3));
    *(uint2*)loP = make_uint2(packbf(l0, l1), packbf(l2, l3));
}

// ==========================================================================
// Tensor-core GEMM (HMMA), R10/R14 structure. BM=128 x BN=64, 2 CTAs/SM.
// MMA issue reordered term-outer: same-acc RAW distance 1 -> 8.
// Per-acc accumulation order unchanged (hh -> hl -> lh): bit-identical.
// ==========================================================================
#define TSTRIDE 80
#define A_TILE  (128 * TSTRIDE)        // 10240
#define B_TILE  (64 * TSTRIDE)         // 5120
#define S_AHI   0
#define S_ALO   A_TILE
#define S_BHI   (2 * A_TILE)
#define S_BLO   (2 * A_TILE + B_TILE)
#define GSMEM   (2 * A_TILE + 2 * B_TILE)   // 30720
#define KCHUNK  32

template <bool SPLIT, bool APRE>
__device__ __forceinline__ void gemm_tc_body(const float* __restrict__ A,
                                             const __nv_bfloat16* __restrict__ Ahig,
                                             const __nv_bfloat16* __restrict__ Alog,
                                             const float* __restrict__ W,
                                             const float* __restrict__ bias,
                                             float* __restrict__ Cf,
                                             __nv_bfloat16* __restrict__ Chi,
                                             __nv_bfloat16* __restrict__ Clo)
{
    __shared__ __align__(128) char smem[GSMEM];
    const uint32_t sbase = smem_u32(smem);

    const int t   = threadIdx.x;
    const int l   = t & 31;
    const int wid = t >> 5;
    const int wm  = wid & 3;
    const int wn  = wid >> 2;
    const int rowBlk = blockIdx.y * 128;
    const int colBlk = blockIdx.x * 64;

    const int lrow = t >> 3;
    const int col4 = (t & 7) * 4;
    const float* Ap = APRE ? nullptr : (A + (size_t)(rowBlk + lrow) * KDIM + col4);
    const __nv_bfloat16* Ahp = APRE ? (Ahig + (size_t)(rowBlk + lrow) * KDIM + col4) : nullptr;
    const __nv_bfloat16* Alp = APRE ? (Alog + (size_t)(rowBlk + lrow) * KDIM + col4) : nullptr;
    const float* Wp = W + (size_t)(colBlk + lrow) * KDIM + col4;
    const uint32_t stoff = (uint32_t)lrow * TSTRIDE + (uint32_t)col4 * 2;

    float acc[2][4][4];
#pragma unroll
    for (int mi = 0; mi < 2; mi++)
#pragma unroll
        for (int ni = 0; ni < 4; ni++)
#pragma unroll
            for (int k = 0; k < 4; k++) acc[mi][ni][k] = 0.f;

    const uint32_t lr  = (uint32_t)(l & 15);
    const uint32_t lcb = (uint32_t)(l >> 4) * 16;
    const uint32_t aBase = sbase + S_AHI + (wm * 32 + lr) * TSTRIDE + lcb;
    const uint32_t bBase = sbase + S_BHI + (wn * 32 + lr) * TSTRIDE + lcb;

    float4 pfA[4], pfB[2];
    uint2  pfAh[4], pfAl[4];
#pragma unroll
    for (int i = 0; i < 4; i++) {
        if (APRE) {
            pfAh[i] = *(const uint2*)(Ahp + (size_t)(i * 32) * KDIM);
            pfAl[i] = *(const uint2*)(Alp + (size_t)(i * 32) * KDIM);
        } else {
            pfA[i] = *(const float4*)(Ap + (size_t)(i * 32) * KDIM);
        }
    }
#pragma unroll
    for (int i = 0; i < 2; i++)
        pfB[i] = *(const float4*)(Wp + (size_t)(i * 32) * KDIM);

    for (int c = 0; c < KCHUNK; c++) {
#pragma unroll
        for (int i = 0; i < 4; i++) {
            const uint32_t o = stoff + (uint32_t)i * (32 * TSTRIDE);
            if (APRE) {
                *(uint2*)(smem + S_AHI + o) = pfAh[i];
                *(uint2*)(smem + S_ALO + o) = pfAl[i];
            } else {
                cvt_split8b(pfA[i], smem + S_AHI + o, smem + S_ALO + o);
            }
        }
#pragma unroll
        for (int i = 0; i < 2; i++) {
            const uint32_t o = stoff + (uint32_t)i * (32 * TSTRIDE);
            cvt_split8b(pfB[i], smem + S_BHI + o, smem + S_BLO + o);
        }
        __syncthreads();

        if (c + 1 < KCHUNK) {
            const int ko = (c + 1) * 32;
#pragma unroll
            for (int i = 0; i < 4; i++) {
                if (APRE) {
                    pfAh[i] = *(const uint2*)(Ahp + (size_t)(i * 32) * KDIM + ko);
                    pfAl[i] = *(const uint2*)(Alp + (size_t)(i * 32) * KDIM + ko);
                } else {
                    pfA[i] = *(const float4*)(Ap + (size_t)(i * 32) * KDIM + ko);
                }
            }
#pragma unroll
            for (int i = 0; i < 2; i++)
                pfB[i] = *(const float4*)(Wp + (size_t)(i * 32) * KDIM + ko);
        }

#pragma unroll
        for (int ks = 0; ks < 2; ks++) {
            const uint32_t ko = (uint32_t)ks * 32;
            uint32_t ah[2][4], al[2][4];
#pragma unroll
            for (int mi = 0; mi < 2; mi++) {
                ldsm4(ah[mi], aBase + mi * (16 * TSTRIDE) + ko);
                ldsm4(al[mi], aBase + A_TILE + mi * (16 * TSTRIDE) + ko);
            }
            uint32_t bh[2][4], bl[2][4];
#pragma unroll
            for (int g = 0; g < 2; g++) {
                ldsm4(bh[g], bBase + g * (16 * TSTRIDE) + ko);
                ldsm4(bl[g], bBase + B_TILE + g * (16 * TSTRIDE) + ko);
            }
            // term-outer issue order: 8 independent accs between dependents
#pragma unroll
            for (int mi = 0; mi < 2; mi++)
#pragma unroll
                for (int ni = 0; ni < 4; ni++) {
                    const int g = ni >> 1, s = ni & 1;
                    mma16816(acc[mi][ni], ah[mi], bh[g][s], bh[g][s + 2]);
                }
#pragma unroll
            for (int mi = 0; mi < 2; mi++)
#pragma unroll
                for (int ni = 0; ni < 4; ni++) {
                    const int g = ni >> 1, s = ni & 1;
                    mma16816(acc[mi][ni], ah[mi], bl[g][s], bl[g][s + 2]);
                }
#pragma unroll
            for (int mi = 0; mi < 2; mi++)
#pragma unroll
                for (int ni = 0; ni < 4; ni++) {
                    const int g = ni >> 1, s = ni & 1;
                    mma16816(acc[mi][ni], al[mi], bh[g][s], bh[g][s + 2]);
                }
        }
        __syncthreads();
    }

#pragma unroll
    for (int mi = 0; mi < 2; mi++) {
        const int rBase = rowBlk + wm * 32 + mi * 16 + (l >> 2);
#pragma unroll
        for (int ni = 0; ni < 4; ni++) {
            const int n = colBlk + wn * 32 + ni * 8 + (l & 3) * 2;
            const float2 bb = *(const float2*)(bias + n);
#pragma unroll
            for (int h2 = 0; h2 < 2; h2++) {
                const int m = rBase + h2 * 8;
                float2 v;
                v.x = acc[mi][ni][h2 * 2 + 0] + bb.x;
                v.y = acc[mi][ni][h2 * 2 + 1] + bb.y;
                if (SPLIT) {
                    const int b = m >> 11;
                    const int s = m & (SEQ - 1);
                    const int h = n >> 6;
                    const int d = n & (DK - 1);
                    const size_t idx = (((size_t)(b * NUM_HEADS + h) * SEQ + s) * DK) + d;
                    if (Chi == nullptr) {
                        *(float2*)&Cf[idx] = v;
                    } else {
                        __nv_bfloat16 hx = __float2bfloat16(v.x);
                        __nv_bfloat16 hy = __float2bfloat16(v.y);
                        __nv_bfloat16 lx = __float2bfloat16(v.x - __bfloat162float(hx));
                        __nv_bfloat16 ly = __float2bfloat16(v.y - __bfloat162float(hy));
                        *(uint32_t*)&Chi[idx] = packbf(hx, hy);
                        *(uint32_t*)&Clo[idx] = packbf(lx, ly);
                    }
                } else {
                    *(float2*)&Cf[(size_t)m * DMODEL + n] = v;
                }
            }
        }
    }
}

__global__ __launch_bounds__(256, 2)
void qkv_tc_kernel(const float* __restrict__ Qin,
                   const float* __restrict__ Kin,
                   const float* __restrict__ Vin,
                   const float* __restrict__ Wq, const float* __restrict__ bq,
                   const float* __restrict__ Wk, const float* __restrict__ bk,
                   const float* __restrict__ Wv, const float* __restrict__ bv)
{
    const int z = blockIdx.z;
    if (z == 0) {
        gemm_tc_body<true, false>(Qin, nullptr, nullptr, Wq, bq, g_Q, nullptr, nullptr);
    } else if (z == 1) {
        gemm_tc_body<true, false>(Kin, nullptr, nullptr, Wk, bk, nullptr, g_Khi, g_Klo);
    } else {
        gemm_tc_body<true, false>(Vin, nullptr, nullptr, Wv, bv, nullptr, g_Vhi, g_Vlo);
    }
}

__global__ __launch_bounds__(256, 2)
void out_tc_kernel(const float* __restrict__ Wo,
                   const float* __restrict__ bo,
                   float* __restrict__ out)
{
    gemm_tc_body<false, true>(nullptr, g_Ohi, g_Olo, Wo, bo, out, nullptr, nullptr);
}

// ==========================================================================
// Flash attention (bf16x3), 2 CTAs/SM, base-2 softmax. MMA issue interleaved
// across the two ss accumulators (RAW distance 1 -> 2); per-acc order kept.
// ==========================================================================
#define FSTR    144
#define FT      (64 * FSTR)            // 9216
#define FQ_HI   0
#define FQ_LO   18432
#define FKV     36864
#define F_KHI   (FKV + 0)
#define F_KLO   (FKV + FT)
#define F_VHI   (FKV + 2 * FT)
#define F_VLO   (FKV + 3 * FT)
#define FSMEM   (FKV + 4 * FT)         // 73728

__global__ __launch_bounds__(256, 2)
void flash_tc_kernel()
{
    extern __shared__ __align__(128) char fsm[];
    const uint32_t sbase = smem_u32(fsm);

    const int t  = threadIdx.x;
    const int l  = t & 31;
    const int w  = t >> 5;
    const int q0 = blockIdx.x * 128;
    const int h  = blockIdx.y;
    const int b  = blockIdx.z;

    const size_t headBase = ((size_t)b * NUM_HEADS + h) * SEQ * DK;
    const float*         Qg  = g_Q   + headBase;
    const __nv_bfloat16* Khi = g_Khi + headBase;
    const __nv_bfloat16* Klo = g_Klo + headBase;
    const __nv_bfloat16* Vhi = g_Vhi + headBase;
    const __nv_bfloat16* Vlo = g_Vlo + headBase;

    const float SCALE2 = 0.125f * 1.4426950408889634f;

    {
        const int row  = t >> 1;
        const int half = (t & 1) * 32;
#pragma unroll
        for (int i = 0; i < 8; i++) {
            float4 q = *(const float4*)&Qg[(size_t)(q0 + row) * DK + half + 4 * i];
            q.x *= SCALE2; q.y *= SCALE2; q.z *= SCALE2; q.w *= SCALE2;
            const uint32_t o = (uint32_t)row * FSTR + (uint32_t)(half + 4 * i) * 2;
            cvt_split8b(q, fsm + FQ_HI + o, fsm + FQ_LO + o);
        }
    }

    float o_[8][4];
#pragma unroll
    for (int j = 0; j < 8; j++)
#pragma unroll
        for (int k = 0; k < 4; k++) o_[j][k] = 0.f;
    float m0 = -1e30f, m1 = -1e30f, l0 = 0.f, l1 = 0.f;

    const uint32_t qbase = sbase + (uint32_t)(w * 16 + (l & 15)) * FSTR
                         + (uint32_t)(l >> 4) * 16;
    const uint32_t lbase = sbase + (uint32_t)(l & 15) * FSTR
                         + (uint32_t)(l >> 4) * 16;
    const uint32_t voff  = (uint32_t)((((l >> 4) & 1) * 8 + (l & 7))) * FSTR
                         + (uint32_t)((l >> 3) & 1) * 16;

    for (int j0 = 0; j0 < SEQ; j0 += 64) {
        {
            const int key = t >> 2;
            const int gr  = (t & 3) * 16;
            const char* kh = (const char*)(Khi + (size_t)(j0 + key) * DK);
            const char* kl = (const char*)(Klo + (size_t)(j0 + key) * DK);
            const char* vh = (const char*)(Vhi + (size_t)(j0 + key) * DK);
            const char* vl = (const char*)(Vlo + (size_t)(j0 + key) * DK);
            const uint32_t so = (uint32_t)key * FSTR;
#pragma unroll
            for (int p = 0; p < 2; p++) {
                const uint32_t cb = (uint32_t)gr + p * 64;
                *(uint4*)(fsm + F_KHI + so + cb) = *(const uint4*)(kh + cb);
                *(uint4*)(fsm + F_KLO + so + cb) = *(const uint4*)(kl + cb);
                *(uint4*)(fsm + F_VHI + so + cb) = *(const uint4*)(vh + cb);
                *(uint4*)(fsm + F_VLO + so + cb) = *(const uint4*)(vl + cb);
            }
        }
        __syncthreads();

        float s[8][4];
#pragma unroll
        for (int j = 0; j < 8; j++)
#pragma unroll
            for (int k = 0; k < 4; k++) s[j][k] = 0.f;

#pragma unroll
        for (int kt = 0; kt < 4; kt++) {
            uint32_t qh[4], ql[4];
            ldsm4(qh, qbase + FQ_HI + kt * 32);
            ldsm4(ql, qbase + FQ_LO + kt * 32);
#pragma unroll
            for (int kg = 0; kg < 4; kg++) {
                uint32_t kh[4], kl[4];
                ldsm4(kh, lbase + F_KHI + kg * (16 * FSTR) + kt * 32);
                ldsm4(kl, lbase + F_KLO + kg * (16 * FSTR) + kt * 32);
                float* sc0 = s[2 * kg + 0];
                float* sc1 = s[2 * kg + 1];
                // interleaved: per-acc order hh -> hl -> lh preserved
                mma16816(sc0, qh, kh[0], kh[2]);
                mma16816(sc1, qh, kh[1], kh[3]);
                mma16816(sc0, qh, kl[0], kl[2]);
                mma16816(sc1, qh, kl[1], kl[3]);
                mma16816(sc0, ql, kh[0], kh[2]);
                mma16816(sc1, ql, kh[1], kh[3]);
            }
        }

        {
            float mx0 = s[0][0], mx1 = s[0][2];
#pragma unroll
            for (int j = 0; j < 8; j++) {
                mx0 = fmaxf(mx0, fmaxf(s[j][0], s[j][1]));
                mx1 = fmaxf(mx1, fmaxf(s[j][2], s[j][3]));
            }
            mx0 = fmaxf(mx0, __shfl_xor_sync(0xffffffffu, mx0, 1));
            mx0 = fmaxf(mx0, __shfl_xor_sync(0xffffffffu, mx0, 2));
            mx1 = fmaxf(mx1, __shfl_xor_sync(0xffffffffu, mx1, 1));
            mx1 = fmaxf(mx1, __shfl_xor_sync(0xffffffffu, mx1, 2));

            const float mn0 = fmaxf(m0, mx0);
            const float mn1 = fmaxf(m1, mx1);
            const float c0 = ex2(m0 - mn0);
            const float c1 = ex2(m1 - mn1);
            m0 = mn0; m1 = mn1;

            float rs0 = 0.f, rs1 = 0.f;
#pragma unroll
            for (int j = 0; j < 8; j++) {
                s[j][0] = ex2(s[j][0] - mn0);
                s[j][1] = ex2(s[j][1] - mn0);
                s[j][2] = ex2(s[j][2] - mn1);
                s[j][3] = ex2(s[j][3] - mn1);
                rs0 += s[j][0] + s[j][1];
                rs1 += s[j][2] + s[j][3];
            }
            rs0 += __shfl_xor_sync(0xffffffffu, rs0, 1);
            rs0 += __shfl_xor_sync(0xffffffffu, rs0, 2);
            rs1 += __shfl_xor_sync(0xffffffffu, rs1, 1);
            rs1 += __shfl_xor_sync(0xffffffffu, rs1, 2);
            l0 = l0 * c0 + rs0;
            l1 = l1 * c1 + rs1;

#pragma unroll
            for (int j = 0; j < 8; j++) {
                o_[j][0] *= c0; o_[j][1] *= c0;
                o_[j][2] *= c1; o_[j][3] *= c1;
            }
        }

#pragma unroll
        for (int kt = 0; kt < 4; kt++) {
            uint32_t phi[4], plo[4];
#pragma unroll
            for (int half = 0; half < 2; half++) {
                const float* sp = s[2 * kt + half];
#pragma unroll
                for (int rr = 0; rr < 2; rr++) {
                    const float x = sp[2 * rr + 0], y = sp[2 * rr + 1];
                    __nv_bfloat16 hx = __float2bfloat16(x);
                    __nv_bfloat16 hy = __float2bfloat16(y);
                    __nv_bfloat16 lx = __float2bfloat16(x - __bfloat162float(hx));
                    __nv_bfloat16 ly = __float2bfloat16(y - __bfloat162float(hy));
                    phi[2 * half + rr] = packbf(hx, hy);
                    plo[2 * half + rr] = packbf(lx, ly);
                }
            }
#pragma unroll
            for (int dg = 0; dg < 4; dg++) {
                uint32_t vh[4], vl[4];
                const uint32_t va = sbase + voff + kt * (16 * FSTR) + dg * 32;
                ldsm4t(vh, va + F_VHI);
                ldsm4t(vl, va + F_VLO);
                float* oc0 = o_[2 * dg + 0];
                float* oc1 = o_[2 * dg + 1];
                mma16816(oc0, phi, vh[0], vh[2]);
                mma16816(oc1, phi, vh[1], vh[3]);
                mma16816(oc0, phi, vl[0], vl[2]);
                mma16816(oc1, phi, vl[1], vl[3]);
                mma16816(oc0, plo, vh[0], vh[2]);
                mma16816(oc1, plo, vh[1], vh[3]);
            }
        }
        __syncthreads();
    }

    {
        const float inv0 = 1.f / l0;
        const float inv1 = 1.f / l1;
        const int r0 = q0 + w * 16 + (l >> 2);
        const int r1 = r0 + 8;
        const size_t ro0 = ((size_t)b * SEQ + r0) * DMODEL;
        const size_t ro1 = ((size_t)b * SEQ + r1) * DMODEL;
#pragma unroll
        for (int j = 0; j < 8; j++) {
            const int d = h * DK + j * 8 + (l & 3) * 2;
            {
                const float x = o_[j][0] * inv0, y = o_[j][1] * inv0;
                __nv_bfloat16 hx = __float2bfloat16(x), hy = __float2bfloat16(y);
                __nv_bfloat16 lx = __float2bfloat16(x - __bfloat162float(hx));
                __nv_bfloat16 ly = __float2bfloat16(y - __bfloat162float(hy));
                *(uint32_t*)&g_Ohi[ro0 + d] = packbf(hx, hy);
                *(uint32_t*)&g_Olo[ro0 + d] = packbf(lx, ly);
            }
            {
                const float x = o_[j][2] * inv1, y = o_[j][3] * inv1;
                __nv_bfloat16 hx = __float2bfloat16(x), hy = __float2bfloat16(y);
                __nv_bfloat16 lx = __float2bfloat16(x - __bfloat162float(hx));
                __nv_bfloat16 ly = __float2bfloat16(y - __bfloat162float(hy));
                *(uint32_t*)&g_Ohi[ro1 + d] = packbf(hx, hy);
                *(uint32_t*)&g_Olo[ro1 + d] = packbf(lx, ly);
            }
        }
    }
}

// ==========================================================================
// launch
// ==========================================================================
extern "C" void kernel_launch(void* const* d_in, const int* in_sizes, int n_in,
                              void* d_out, int out_size)
{
    (void)in_sizes; (void)n_in; (void)out_size;
    const float* Qin = (const float*)d_in[0];
    const float* Kin = (const float*)d_in[1];
    const float* Vin = (const float*)d_in[2];
    const float* Wq  = (const float*)d_in[3];
    const float* bq  = (const float*)d_in[4];
    const float* Wk  = (const float*)d_in[5];
    const float* bk  = (const float*)d_in[6];
    const float* Wv  = (const float*)d_in[7];
    const float* bv  = (const float*)d_in[8];
    const float* Wo  = (const float*)d_in[9];
    const float* bo  = (const float*)d_in[10];
    float* out = (float*)d_out;

    cudaFuncSetAttribute(flash_tc_kernel,
                         cudaFuncAttributeMaxDynamicSharedMemorySize, FSMEM);

    dim3 gProj(DMODEL / 64, MROWS / 128, 3);
    qkv_tc_kernel<<<gProj, 256>>>(Qin, Kin, Vin, Wq, bq, Wk, bk, Wv, bv);

    dim3 gAttn(SEQ / 128, NUM_HEADS, BATCH);
    flash_tc_kernel<<<gAttn, 256, FSMEM>>>();

    dim3 gOut(DMODEL / 64, MROWS / 128, 1);
    out_tc_kernel<<<gOut, 256>>>(Wo, bo, out);
}

// round 17
// speedup vs baseline: 1.0294x; 1.0268x over previous
#include <cuda_runtime.h>
#include <cuda_bf16.h>
#include <math.h>
#include <stdint.h>

#define NUM_HEADS 16
#define DMODEL    1024
#define DK        64
#define BATCH     2
#define SEQ       2048
#define MROWS     (BATCH * SEQ)      // 4096
#define KDIM      1024
#define HSZ       (BATCH * NUM_HEADS * SEQ * DK)   // 4194304

// ---------------- scratch (device globals; no allocation allowed) ----------
__device__ __align__(128) float g_Q[HSZ];                 // fp32 Q [b,h,s,d]
__device__ __align__(128) __nv_bfloat16 g_Khi[HSZ];
__device__ __align__(128) __nv_bfloat16 g_Klo[HSZ];
__device__ __align__(128) __nv_bfloat16 g_Vhi[HSZ];
__device__ __align__(128) __nv_bfloat16 g_Vlo[HSZ];
__device__ __align__(128) __nv_bfloat16 g_Ohi[(size_t)MROWS * DMODEL];
__device__ __align__(128) __nv_bfloat16 g_Olo[(size_t)MROWS * DMODEL];

// ==========================================================================
// warp-MMA helpers (arch-agnostic PTX: valid on plain sm_103 target)
// ==========================================================================
__device__ __forceinline__ uint32_t smem_u32(const void* p) {
    uint32_t a;
    asm("{ .reg .u64 t; cvta.to.shared.u64 t, %1; cvt.u32.u64 %0, t; }"
        : "=r"(a) : "l"(p));
    return a;
}

__device__ __forceinline__ void ldsm4(uint32_t* r, uint32_t addr) {
    asm volatile("ldmatrix.sync.aligned.m8n8.x4.shared.b16 {%0,%1,%2,%3}, [%4];"
                 : "=r"(r[0]), "=r"(r[1]), "=r"(r[2]), "=r"(r[3])
                 : "r"(addr));
}

__device__ __forceinline__ void ldsm4t(uint32_t* r, uint32_t addr) {
    asm volatile("ldmatrix.sync.aligned.m8n8.x4.trans.shared.b16 {%0,%1,%2,%3}, [%4];"
                 : "=r"(r[0]), "=r"(r[1]), "=r"(r[2]), "=r"(r[3])
                 : "r"(addr));
}

__device__ __forceinline__ void mma16816(float* c, const uint32_t* a,
                                         uint32_t b0, uint32_t b1) {
    asm volatile(
        "mma.sync.aligned.m16n8k16.row.col.f32.bf16.bf16.f32 "
        "{%0,%1,%2,%3}, {%4,%5,%6,%7}, {%8,%9}, {%0,%1,%2,%3};"
        : "+f"(c[0]), "+f"(c[1]), "+f"(c[2]), "+f"(c[3])
        : "r"(a[0]), "r"(a[1]), "r"(a[2]), "r"(a[3]), "r"(b0), "r"(b1));
}

__device__ __forceinline__ void cpasync16(uint32_t dst, const void* src) {
    asm volatile("cp.async.cg.shared.global [%0], [%1], 16;"
                 :: "r"(dst), "l"(src) : "memory");
}
__device__ __forceinline__ void cp_commit() {
    asm volatile("cp.async.commit_group;" ::: "memory");
}
template <int N>
__device__ __forceinline__ void cp_wait() {
    asm volatile("cp.async.wait_group %0;" :: "n"(N) : "memory");
}

__device__ __forceinline__ float ex2(float x) {
    float r;
    asm("ex2.approx.ftz.f32 %0, %1;" : "=f"(r) : "f"(x));
    return r;
}

__device__ __forceinline__ uint32_t packbf(__nv_bfloat16 a, __nv_bfloat16 b) {
    return (uint32_t)__bfloat16_as_ushort(a) |
           ((uint32_t)__bfloat16_as_ushort(b) << 16);
}

// fp32x4 -> hi bf16x4 (8B) + lo bf16x4 (8B)
__device__ __forceinline__ void cvt_split8b(float4 v, char* hiP, char* loP) {
    __nv_bfloat16 h0 = __float2bfloat16(v.x);
    __nv_bfloat16 h1 = __float2bfloat16(v.y);
    __nv_bfloat16 h2 = __float2bfloat16(v.z);
    __nv_bfloat16 h3 = __float2bfloat16(v.w);
    __nv_bfloat16 l0 = __float2bfloat16(v.x - __bfloat162float(h0));
    __nv_bfloat16 l1 = __float2bfloat16(v.y - __bfloat162float(h1));
    __nv_bfloat16 l2 = __float2bfloat16(v.z - __bfloat162float(h2));
    __nv_bfloat16 l3 = __float2bfloat16(v.w - __bfloat162float(h3));
    *(uint2*)hiP = make_uint2(packbf(h0, h1), packbf(h2, h3));
    *(uint2*)loP = make_uint2(packbf(l0, l1), packbf(l2, l3));
}

// ==========================================================================
// Tensor-core GEMM (HMMA): R16 version (equal-best). BM=128 x BN=64,
// 2 CTAs/SM, 8 warps 4(m)x2(n).
// ==========================================================================
#define TSTRIDE 80
#define A_TILE  (128 * TSTRIDE)        // 10240
#define B_TILE  (64 * TSTRIDE)         // 5120
#define S_AHI   0
#define S_ALO   A_TILE
#define S_BHI   (2 * A_TILE)
#define S_BLO   (2 * A_TILE + B_TILE)
#define GSMEM   (2 * A_TILE + 2 * B_TILE)   // 30720
#define KCHUNK  32

template <bool SPLIT, bool APRE>
__device__ __forceinline__ void gemm_tc_body(const float* __restrict__ A,
                                             const __nv_bfloat16* __restrict__ Ahig,
                                             const __nv_bfloat16* __restrict__ Alog,
                                             const float* __restrict__ W,
                                             const float* __restrict__ bias,
                                             float* __restrict__ Cf,
                                             __nv_bfloat16* __restrict__ Chi,
                                             __nv_bfloat16* __restrict__ Clo)
{
    __shared__ __align__(128) char smem[GSMEM];
    const uint32_t sbase = smem_u32(smem);

    const int t   = threadIdx.x;
    const int l   = t & 31;
    const int wid = t >> 5;
    const int wm  = wid & 3;
    const int wn  = wid >> 2;
    const int rowBlk = blockIdx.y * 128;
    const int colBlk = blockIdx.x * 64;

    const int lrow = t >> 3;
    const int col4 = (t & 7) * 4;
    const float* Ap = APRE ? nullptr : (A + (size_t)(rowBlk + lrow) * KDIM + col4);
    const __nv_bfloat16* Ahp = APRE ? (Ahig + (size_t)(rowBlk + lrow) * KDIM + col4) : nullptr;
    const __nv_bfloat16* Alp = APRE ? (Alog + (size_t)(rowBlk + lrow) * KDIM + col4) : nullptr;
    const float* Wp = W + (size_t)(colBlk + lrow) * KDIM + col4;
    const uint32_t stoff = (uint32_t)lrow * TSTRIDE + (uint32_t)col4 * 2;

    float acc[2][4][4];
#pragma unroll
    for (int mi = 0; mi < 2; mi++)
#pragma unroll
        for (int ni = 0; ni < 4; ni++)
#pragma unroll
            for (int k = 0; k < 4; k++) acc[mi][ni][k] = 0.f;

    const uint32_t lr  = (uint32_t)(l & 15);
    const uint32_t lcb = (uint32_t)(l >> 4) * 16;
    const uint32_t aBase = sbase + S_AHI + (wm * 32 + lr) * TSTRIDE + lcb;
    const uint32_t bBase = sbase + S_BHI + (wn * 32 + lr) * TSTRIDE + lcb;

    float4 pfA[4], pfB[2];
    uint2  pfAh[4], pfAl[4];
#pragma unroll
    for (int i = 0; i < 4; i++) {
        if (APRE) {
            pfAh[i] = *(const uint2*)(Ahp + (size_t)(i * 32) * KDIM);
            pfAl[i] = *(const uint2*)(Alp + (size_t)(i * 32) * KDIM);
        } else {
            pfA[i] = *(const float4*)(Ap + (size_t)(i * 32) * KDIM);
        }
    }
#pragma unroll
    for (int i = 0; i < 2; i++)
        pfB[i] = *(const float4*)(Wp + (size_t)(i * 32) * KDIM);

    for (int c = 0; c < KCHUNK; c++) {
#pragma unroll
        for (int i = 0; i < 4; i++) {
            const uint32_t o = stoff + (uint32_t)i * (32 * TSTRIDE);
            if (APRE) {
                *(uint2*)(smem + S_AHI + o) = pfAh[i];
                *(uint2*)(smem + S_ALO + o) = pfAl[i];
            } else {
                cvt_split8b(pfA[i], smem + S_AHI + o, smem + S_ALO + o);
            }
        }
#pragma unroll
        for (int i = 0; i < 2; i++) {
            const uint32_t o = stoff + (uint32_t)i * (32 * TSTRIDE);
            cvt_split8b(pfB[i], smem + S_BHI + o, smem + S_BLO + o);
        }
        __syncthreads();

        if (c + 1 < KCHUNK) {
            const int ko = (c + 1) * 32;
#pragma unroll
            for (int i = 0; i < 4; i++) {
                if (APRE) {
                    pfAh[i] = *(const uint2*)(Ahp + (size_t)(i * 32) * KDIM + ko);
                    pfAl[i] = *(const uint2*)(Alp + (size_t)(i * 32) * KDIM + ko);
                } else {
                    pfA[i] = *(const float4*)(Ap + (size_t)(i * 32) * KDIM + ko);
                }
            }
#pragma unroll
            for (int i = 0; i < 2; i++)
                pfB[i] = *(const float4*)(Wp + (size_t)(i * 32) * KDIM + ko);
        }

#pragma unroll
        for (int ks = 0; ks < 2; ks++) {
            const uint32_t ko = (uint32_t)ks * 32;
            uint32_t ah[2][4], al[2][4];
#pragma unroll
            for (int mi = 0; mi < 2; mi++) {
                ldsm4(ah[mi], aBase + mi * (16 * TSTRIDE) + ko);
                ldsm4(al[mi], aBase + A_TILE + mi * (16 * TSTRIDE) + ko);
            }
            uint32_t bh[2][4], bl[2][4];
#pragma unroll
            for (int g = 0; g < 2; g++) {
                ldsm4(bh[g], bBase + g * (16 * TSTRIDE) + ko);
                ldsm4(bl[g], bBase + B_TILE + g * (16 * TSTRIDE) + ko);
            }
#pragma unroll
            for (int mi = 0; mi < 2; mi++)
#pragma unroll
                for (int ni = 0; ni < 4; ni++) {
                    const int g = ni >> 1, s = ni & 1;
                    mma16816(acc[mi][ni], ah[mi], bh[g][s], bh[g][s + 2]);
                }
#pragma unroll
            for (int mi = 0; mi < 2; mi++)
#pragma unroll
                for (int ni = 0; ni < 4; ni++) {
                    const int g = ni >> 1, s = ni & 1;
                    mma16816(acc[mi][ni], ah[mi], bl[g][s], bl[g][s + 2]);
                }
#pragma unroll
            for (int mi = 0; mi < 2; mi++)
#pragma unroll
                for (int ni = 0; ni < 4; ni++) {
                    const int g = ni >> 1, s = ni & 1;
                    mma16816(acc[mi][ni], al[mi], bh[g][s], bh[g][s + 2]);
                }
        }
        __syncthreads();
    }

#pragma unroll
    for (int mi = 0; mi < 2; mi++) {
        const int rBase = rowBlk + wm * 32 + mi * 16 + (l >> 2);
#pragma unroll
        for (int ni = 0; ni < 4; ni++) {
            const int n = colBlk + wn * 32 + ni * 8 + (l & 3) * 2;
            const float2 bb = *(const float2*)(bias + n);
#pragma unroll
            for (int h2 = 0; h2 < 2; h2++) {
                const int m = rBase + h2 * 8;
                float2 v;
                v.x = acc[mi][ni][h2 * 2 + 0] + bb.x;
                v.y = acc[mi][ni][h2 * 2 + 1] + bb.y;
                if (SPLIT) {
                    const int b = m >> 11;
                    const int s = m & (SEQ - 1);
                    const int h = n >> 6;
                    const int d = n & (DK - 1);
                    const size_t idx = (((size_t)(b * NUM_HEADS + h) * SEQ + s) * DK) + d;
                    if (Chi == nullptr) {
                        *(float2*)&Cf[idx] = v;
                    } else {
                        __nv_bfloat16 hx = __float2bfloat16(v.x);
                        __nv_bfloat16 hy = __float2bfloat16(v.y);
                        __nv_bfloat16 lx = __float2bfloat16(v.x - __bfloat162float(hx));
                        __nv_bfloat16 ly = __float2bfloat16(v.y - __bfloat162float(hy));
                        *(uint32_t*)&Chi[idx] = packbf(hx, hy);
                        *(uint32_t*)&Clo[idx] = packbf(lx, ly);
                    }
                } else {
                    *(float2*)&Cf[(size_t)m * DMODEL + n] = v;
                }
            }
        }
    }
}

__global__ __launch_bounds__(256, 2)
void qkv_tc_kernel(const float* __restrict__ Qin,
                   const float* __restrict__ Kin,
                   const float* __restrict__ Vin,
                   const float* __restrict__ Wq, const float* __restrict__ bq,
                   const float* __restrict__ Wk, const float* __restrict__ bk,
                   const float* __restrict__ Wv, const float* __restrict__ bv)
{
    const int z = blockIdx.z;
    if (z == 0) {
        gemm_tc_body<true, false>(Qin, nullptr, nullptr, Wq, bq, g_Q, nullptr, nullptr);
    } else if (z == 1) {
        gemm_tc_body<true, false>(Kin, nullptr, nullptr, Wk, bk, nullptr, g_Khi, g_Klo);
    } else {
        gemm_tc_body<true, false>(Vin, nullptr, nullptr, Wv, bv, nullptr, g_Vhi, g_Vlo);
    }
}

__global__ __launch_bounds__(256, 2)
void out_tc_kernel(const float* __restrict__ Wo,
                   const float* __restrict__ bo,
                   float* __restrict__ out)
{
    gemm_tc_body<false, true>(nullptr, g_Ohi, g_Olo, Wo, bo, out, nullptr, nullptr);
}

// ==========================================================================
// Flash attention (bf16x3), 2 CTAs/SM, base-2 softmax, cp.async
// double-buffered K/V tiles: one barrier per tile, loads issued one full
// tile ahead and landing during the previous tile's MMA block.
// smem/CTA: Q 36864 + 2 x KV 36864 = 110592.
// ==========================================================================
#define FSTR    144
#define FT      (64 * FSTR)            // 9216
#define FQ_HI   0
#define FQ_LO   18432
#define FKV     36864                  // buffer 0 base; buffer 1 at FKV+KVBUF
#define KVBUF   (4 * FT)               // 36864
#define F_KHI   0
#define F_KLO   FT
#define F_VHI   (2 * FT)
#define F_VLO   (3 * FT)
#define FSMEM   (FKV + 2 * KVBUF)      // 110592
#define NTILES  (SEQ / 64)             // 32

__global__ __launch_bounds__(256, 2)
void flash_tc_kernel()
{
    extern __shared__ __align__(128) char fsm[];
    const uint32_t sbase = smem_u32(fsm);

    const int t  = threadIdx.x;
    const int l  = t & 31;
    const int w  = t >> 5;
    const int q0 = blockIdx.x * 128;
    const int h  = blockIdx.y;
    const int b  = blockIdx.z;

    const size_t headBase = ((size_t)b * NUM_HEADS + h) * SEQ * DK;
    const float*         Qg  = g_Q   + headBase;
    const __nv_bfloat16* Khi = g_Khi + headBase;
    const __nv_bfloat16* Klo = g_Klo + headBase;
    const __nv_bfloat16* Vhi = g_Vhi + headBase;
    const __nv_bfloat16* Vlo = g_Vlo + headBase;

    const float SCALE2 = 0.125f * 1.4426950408889634f;

    // copy-thread mapping (per tile: 8 cp.async x 16B per thread)
    const int key = t >> 2;
    const int gr  = (t & 3) * 16;
    const uint32_t so = (uint32_t)key * FSTR;

    auto issue = [&](int jt) {
        if (jt < NTILES) {
            const uint32_t buf = sbase + FKV + (uint32_t)(jt & 1) * KVBUF;
            const size_t roff = (size_t)(jt * 64 + key) * DK;
            const char* kh = (const char*)(Khi + roff);
            const char* kl = (const char*)(Klo + roff);
            const char* vh = (const char*)(Vhi + roff);
            const char* vl = (const char*)(Vlo + roff);
#pragma unroll
            for (int p = 0; p < 2; p++) {
                const uint32_t cb = (uint32_t)gr + p * 64;
                cpasync16(buf + F_KHI + so + cb, kh + cb);
                cpasync16(buf + F_KLO + so + cb, kl + cb);
                cpasync16(buf + F_VHI + so + cb, vh + cb);
                cpasync16(buf + F_VLO + so + cb, vl + cb);
            }
        }
        cp_commit();
    };

    // ---- stage Q (scaled) hi/lo into persistent smem; kick off tile 0 ----
    issue(0);
    {
        const int row  = t >> 1;
        const int half = (t & 1) * 32;
#pragma unroll
        for (int i = 0; i < 8; i++) {
            float4 q = *(const float4*)&Qg[(size_t)(q0 + row) * DK + half + 4 * i];
            q.x *= SCALE2; q.y *= SCALE2; q.z *= SCALE2; q.w *= SCALE2;
            const uint32_t o = (uint32_t)row * FSTR + (uint32_t)(half + 4 * i) * 2;
            cvt_split8b(q, fsm + FQ_HI + o, fsm + FQ_LO + o);
        }
    }

    float o_[8][4];
#pragma unroll
    for (int j = 0; j < 8; j++)
#pragma unroll
        for (int k = 0; k < 4; k++) o_[j][k] = 0.f;
    float m0 = -1e30f, m1 = -1e30f, l0 = 0.f, l1 = 0.f;

    const uint32_t qbase = sbase + (uint32_t)(w * 16 + (l & 15)) * FSTR
                         + (uint32_t)(l >> 4) * 16;
    const uint32_t lOff  = (uint32_t)(l & 15) * FSTR + (uint32_t)(l >> 4) * 16;
    const uint32_t vOff  = (uint32_t)((((l >> 4) & 1) * 8 + (l & 7))) * FSTR
                         + (uint32_t)((l >> 3) & 1) * 16;

    for (int jt = 0; jt < NTILES; jt++) {
        cp_wait<0>();          // this thread's copies for tile jt complete
        __syncthreads();       // all threads' copies visible; prior-tile reads done
        issue(jt + 1);         // refill other buffer (lands during MMA below)

        const uint32_t cbuf = sbase + FKV + (uint32_t)(jt & 1) * KVBUF;

        // ---- S2 = (Q*scale*log2e) @ K^T  (bf16x3) ----
        float s[8][4];
#pragma unroll
        for (int j = 0; j < 8; j++)
#pragma unroll
            for (int k = 0; k < 4; k++) s[j][k] = 0.f;

#pragma unroll
        for (int kt = 0; kt < 4; kt++) {
            uint32_t qh[4], ql[4];
            ldsm4(qh, qbase + FQ_HI + kt * 32);
            ldsm4(ql, qbase + FQ_LO + kt * 32);
#pragma unroll
            for (int kg = 0; kg < 4; kg++) {
                uint32_t kh[4], kl[4];
                ldsm4(kh, cbuf + lOff + F_KHI + kg * (16 * FSTR) + kt * 32);
                ldsm4(kl, cbuf + lOff + F_KLO + kg * (16 * FSTR) + kt * 32);
                float* sc0 = s[2 * kg + 0];
                float* sc1 = s[2 * kg + 1];
                mma16816(sc0, qh, kh[0], kh[2]);
                mma16816(sc1, qh, kh[1], kh[3]);
                mma16816(sc0, qh, kl[0], kl[2]);
                mma16816(sc1, qh, kl[1], kl[3]);
                mma16816(sc0, ql, kh[0], kh[2]);
                mma16816(sc1, ql, kh[1], kh[3]);
            }
        }

        // ---- online softmax (base-2 domain) ----
        {
            float mx0 = s[0][0], mx1 = s[0][2];
#pragma unroll
            for (int j = 0; j < 8; j++) {
                mx0 = fmaxf(mx0, fmaxf(s[j][0], s[j][1]));
                mx1 = fmaxf(mx1, fmaxf(s[j][2], s[j][3]));
            }
            mx0 = fmaxf(mx0, __shfl_xor_sync(0xffffffffu, mx0, 1));
            mx0 = fmaxf(mx0, __shfl_xor_sync(0xffffffffu, mx0, 2));
            mx1 = fmaxf(mx1, __shfl_xor_sync(0xffffffffu, mx1, 1));
            mx1 = fmaxf(mx1, __shfl_xor_sync(0xffffffffu, mx1, 2));

            const float mn0 = fmaxf(m0, mx0);
            const float mn1 = fmaxf(m1, mx1);
            const float c0 = ex2(m0 - mn0);
            const float c1 = ex2(m1 - mn1);
            m0 = mn0; m1 = mn1;

            float rs0 = 0.f, rs1 = 0.f;
#pragma unroll
            for (int j = 0; j < 8; j++) {
                s[j][0] = ex2(s[j][0] - mn0);
                s[j][1] = ex2(s[j][1] - mn0);
                s[j][2] = ex2(s[j][2] - mn1);
                s[j][3] = ex2(s[j][3] - mn1);
                rs0 += s[j][0] + s[j][1];
                rs1 += s[j][2] + s[j][3];
            }
            rs0 += __shfl_xor_sync(0xffffffffu, rs0, 1);
            rs0 += __shfl_xor_sync(0xffffffffu, rs0, 2);
            rs1 += __shfl_xor_sync(0xffffffffu, rs1, 1);
            rs1 += __shfl_xor_sync(0xffffffffu, rs1, 2);
            l0 = l0 * c0 + rs0;
            l1 = l1 * c1 + rs1;

#pragma unroll
            for (int j = 0; j < 8; j++) {
                o_[j][0] *= c0; o_[j][1] *= c0;
                o_[j][2] *= c1; o_[j][3] *= c1;
            }
        }

        // ---- O += P @ V  (bf16x3; V via trans ldmatrix on [key][d]) ----
#pragma unroll
        for (int kt = 0; kt < 4; kt++) {
            uint32_t phi[4], plo[4];
#pragma unroll
            for (int half = 0; half < 2; half++) {
                const float* sp = s[2 * kt + half];
#pragma unroll
                for (int rr = 0; rr < 2; rr++) {
                    const float x = sp[2 * rr + 0], y = sp[2 * rr + 1];
                    __nv_bfloat16 hx = __float2bfloat16(x);
                    __nv_bfloat16 hy = __float2bfloat16(y);
                    __nv_bfloat16 lx = __float2bfloat16(x - __bfloat162float(hx));
                    __nv_bfloat16 ly = __float2bfloat16(y - __bfloat162float(hy));
                    phi[2 * half + rr] = packbf(hx, hy);
                    plo[2 * half + rr] = packbf(lx, ly);
                }
            }
#pragma unroll
            for (int dg = 0; dg < 4; dg++) {
                uint32_t vh[4], vl[4];
                const uint32_t va = cbuf + vOff + kt * (16 * FSTR) + dg * 32;
                ldsm4t(vh, va + F_VHI);
                ldsm4t(vl, va + F_VLO);
                float* oc0 = o_[2 * dg + 0];
                float* oc1 = o_[2 * dg + 1];
                mma16816(oc0, phi, vh[0], vh[2]);
                mma16816(oc1, phi, vh[1], vh[3]);
                mma16816(oc0, phi, vl[0], vl[2]);
                mma16816(oc1, phi, vl[1], vl[3]);
                mma16816(oc0, plo, vh[0], vh[2]);
                mma16816(oc1, plo, vh[1], vh[3]);
            }
        }
        // no trailing barrier: next iteration's collective sync orders all
        // warps' reads of this buffer before its refill (issued 2 tiles on)
    }

    // ---- epilogue: normalize, write bf16 hi/lo merged-head [b*S, DMODEL] --
    {
        const float inv0 = 1.f / l0;
        const float inv1 = 1.f / l1;
        const int r0 = q0 + w * 16 + (l >> 2);
        const int r1 = r0 + 8;
        const size_t ro0 = ((size_t)b * SEQ + r0) * DMODEL;
        const size_t ro1 = ((size_t)b * SEQ + r1) * DMODEL;
#pragma unroll
        for (int j = 0; j < 8; j++) {
            const int d = h * DK + j * 8 + (l & 3) * 2;
            {
                const float x = o_[j][0] * inv0, y = o_[j][1] * inv0;
                __nv_bfloat16 hx = __float2bfloat16(x), hy = __float2bfloat16(y);
                __nv_bfloat16 lx = __float2bfloat16(x - __bfloat162float(hx));
                __nv_bfloat16 ly = __float2bfloat16(y - __bfloat162float(hy));
                *(uint32_t*)&g_Ohi[ro0 + d] = packbf(hx, hy);
                *(uint32_t*)&g_Olo[ro0 + d] = packbf(lx, ly);
            }
            {
                const float x = o_[j][2] * inv1, y = o_[j][3] * inv1;
                __nv_bfloat16 hx = __float2bfloat16(x), hy = __float2bfloat16(y);
                __nv_bfloat16 lx = __float2bfloat16(x - __bfloat162float(hx));
                __nv_bfloat16 ly = __float2bfloat16(y - __bfloat162float(hy));
                *(uint32_t*)&g_Ohi[ro1 + d] = packbf(hx, hy);
                *(uint32_t*)&g_Olo[ro1 + d] = packbf(lx, ly);
            }
        }
    }
}

// ==========================================================================
// launch
// ==========================================================================
extern "C" void kernel_launch(void* const* d_in, const int* in_sizes, int n_in,
                              void* d_out, int out_size)
{
    (void)in_sizes; (void)n_in; (void)out_size;
    const float* Qin = (const float*)d_in[0];
    const float* Kin = (const float*)d_in[1];
    const float* Vin = (const float*)d_in[2];
    const float* Wq  = (const float*)d_in[3];
    const float* bq  = (const float*)d_in[4];
    const float* Wk  = (const float*)d_in[5];
    const float* bk  = (const float*)d_in[6];
    const float* Wv  = (const float*)d_in[7];
    const float* bv  = (const float*)d_in[8];
    const float* Wo  = (const float*)d_in[9];
    const float* bo  = (const float*)d_in[10];
    float* out = (float*)d_out;

    cudaFuncSetAttribute(flash_tc_kernel,
                         cudaFuncAttributeMaxDynamicSharedMemorySize, FSMEM);

    dim3 gProj(DMODEL / 64, MROWS / 128, 3);
    qkv_tc_kernel<<<gProj, 256>>>(Qin, Kin, Vin, Wq, bq, Wk, bk, Wv, bv);

    dim3 gAttn(SEQ / 128, NUM_HEADS, BATCH);
    flash_tc_kernel<<<gAttn, 256, FSMEM>>>();

    dim3 gOut(DMODEL / 64, MROWS / 128, 1);
    out_tc_kernel<<<gOut, 256>>>(Wo, bo, out);
}